// round 14
// baseline (speedup 1.0000x reference)
#include <cuda_runtime.h>
#include <cuda_fp16.h>
#include <math.h>
#include <stdint.h>

// Problem shape (fixed): inputs [4096,512] fp32, targets [4096] int32.
#define N 4096
#define D 512
#define MARGIN 1.0f

#define TILE 128
#define NTILES (N / TILE)                         // 32
#define NPAIR_TILES (NTILES * (NTILES + 1) / 2)   // 528
#define KTOT 512                                  // single-pass fp16
#define KCH 64                                    // fp16 per K-stage (128 B/row)
#define NCHUNK (KTOT / KCH)                       // 8
#define GTHREADS 256
#define PGRID 296                                 // 2 CTAs/SM x 148 SMs
#define CAP 1024                                  // smem positive-pair buffer per CTA
#define LGRID 256                                 // loss kernel grid

#define MAXPOS (N * (N - 1) / 2)

// ---------------- device scratch (no allocations allowed) ----------------
__device__ float g_mag[N];
__device__ float g_rowneg[N];
__device__ double g_loss;
__device__ unsigned g_npos;
__device__ unsigned g_ldone;
__device__ unsigned g_pos_key[MAXPOS];  // (i << 12) | j, i < j
__device__ float g_pos_dist[MAXPOS];
__device__ __half g_Xh[(size_t)N * KTOT];

// ---------------- PTX helpers (baseline PTX only: sm_80+ features) ----------------
__device__ __forceinline__ uint32_t smem_u32(const void* p) {
    uint32_t a;
    asm("{ .reg .u64 t; cvta.to.shared.u64 t, %1; cvt.u32.u64 %0, t; }"
        : "=r"(a) : "l"(p));
    return a;
}

#define CP_ASYNC16(dst, src) \
    asm volatile("cp.async.cg.shared.global [%0], [%1], 16;" \
                 :: "r"(dst), "l"(src) : "memory")
#define CP_COMMIT() asm volatile("cp.async.commit_group;" ::: "memory")
#define CP_WAIT(n)  asm volatile("cp.async.wait_group %0;" :: "n"(n) : "memory")

__device__ __forceinline__ void ldmatrix_x4(uint32_t& r0, uint32_t& r1,
                                            uint32_t& r2, uint32_t& r3,
                                            uint32_t addr) {
    asm volatile("ldmatrix.sync.aligned.m8n8.x4.shared.b16 {%0,%1,%2,%3}, [%4];"
                 : "=r"(r0), "=r"(r1), "=r"(r2), "=r"(r3) : "r"(addr));
}
__device__ __forceinline__ void ldmatrix_x2(uint32_t& r0, uint32_t& r1,
                                            uint32_t addr) {
    asm volatile("ldmatrix.sync.aligned.m8n8.x2.shared.b16 {%0,%1}, [%2];"
                 : "=r"(r0), "=r"(r1) : "r"(addr));
}
__device__ __forceinline__ void mma_f16(float* d, const uint32_t* a,
                                        const uint32_t* b) {
    asm volatile(
        "mma.sync.aligned.m16n8k16.row.col.f32.f16.f16.f32 "
        "{%0,%1,%2,%3}, {%4,%5,%6,%7}, {%8,%9}, {%0,%1,%2,%3};"
        : "+f"(d[0]), "+f"(d[1]), "+f"(d[2]), "+f"(d[3])
        : "r"(a[0]), "r"(a[1]), "r"(a[2]), "r"(a[3]), "r"(b[0]), "r"(b[1]));
}

__device__ __forceinline__ uint32_t swz(uint32_t off) {
    return off ^ ((off >> 3) & 0x70);
}

// ---------------- prep: mag + fp16 convert + counter init ----------------
// 256 blocks x 8 warps; each WARP owns TWO rows interleaved (MLP 8/lane).
__global__ void k_prep(const float* __restrict__ X) {
    const int tid = threadIdx.x;      // 256
    const int wid = tid >> 5;
    const int lid = tid & 31;
    const int i0 = blockIdx.x * 16 + wid * 2;
    const int i1 = i0 + 1;

    const float4* x0 = (const float4*)(X + (size_t)i0 * D);
    const float4* x1 = (const float4*)(X + (size_t)i1 * D);
    __half2* p0 = (__half2*)(g_Xh + (size_t)i0 * KTOT);
    __half2* p1 = (__half2*)(g_Xh + (size_t)i1 * KTOT);

    float s0 = 0.0f, s1 = 0.0f;
#pragma unroll
    for (int c = 0; c < 4; c++) {
        float4 v0 = x0[lid + c * 32];
        float4 v1 = x1[lid + c * 32];
        s0 += v0.x * v0.x + v0.y * v0.y + v0.z * v0.z + v0.w * v0.w;
        s1 += v1.x * v1.x + v1.y * v1.y + v1.z * v1.z + v1.w * v1.w;
        p0[(lid + c * 32) * 2 + 0] = __floats2half2_rn(v0.x, v0.y);
        p0[(lid + c * 32) * 2 + 1] = __floats2half2_rn(v0.z, v0.w);
        p1[(lid + c * 32) * 2 + 0] = __floats2half2_rn(v1.x, v1.y);
        p1[(lid + c * 32) * 2 + 1] = __floats2half2_rn(v1.z, v1.w);
    }
    for (int o = 16; o > 0; o >>= 1) {
        s0 += __shfl_down_sync(0xffffffffu, s0, o);
        s1 += __shfl_down_sync(0xffffffffu, s1, o);
    }
    if (lid == 0) {
        g_mag[i0] = s0;
        g_mag[i1] = s1;
        g_rowneg[i0] = 0.0f;
        g_rowneg[i1] = 0.0f;
        if (i0 == 0) { g_loss = 0.0; g_npos = 0u; g_ldone = 0u; }
    }
}

// ---------------- main pass: PERSISTENT HMMA symmetric GEMM + fused epilogue ----
// 8 warps, each owns a 64x32 sub-tile (warp grid 2x4) via m16n8k16 fp16 MMA.
// R9 tile body, wrapped in a persistent loop (grid = 296 = 2/SM) to remove
// wave quantization (528 tiles / 296 slots = 1.78 waves). NO finisher here —
// R5/R12 proved a fused finisher spills the mainloop.
__global__ void __launch_bounds__(GTHREADS, 2)
k_gemm(const int* __restrict__ lab) {
    __shared__ float sMagI[TILE], sMagJ[TILE];
    __shared__ int sLabI[TILE], sLabJ[TILE];
    __shared__ float sRow[TILE], sCol[TILE];
    __shared__ unsigned sPosKey[CAP];
    __shared__ float sPosDist[CAP];
    __shared__ unsigned sNpos, sBase;
    extern __shared__ char dsm[];

    const int tid = threadIdx.x;
    const int wid = tid >> 5;
    const int lid = tid & 31;
    const int wm = wid >> 2;      // warp row 0..1 -> m offset 0/64
    const int wn = wid & 3;       // warp col 0..3 -> n offset 0/32/64/96
    const int m0w = wm * 64;
    const int n0w = wn * 32;

    // dynamic smem: [A0(16K) B0(16K) A1(16K) B1(16K)], 1024-aligned
    const uint32_t tbase = (smem_u32(dsm) + 1023u) & ~1023u;

    // per-thread load coords (4 x 16B chunks per tile per stage)
    const int lrow[4] = {(tid + 0) >> 3, (tid + 256) >> 3, (tid + 512) >> 3, (tid + 768) >> 3};
    const int lkc = tid & 7;

#pragma unroll 1
    for (int bid = blockIdx.x; bid < NPAIR_TILES; bid += PGRID) {
        // decode upper-triangle tile (bi <= bj)
        int t = bid, bi = 0;
        while (t >= NTILES - bi) { t -= NTILES - bi; bi++; }
        const int bj = bi + t;
        const bool diag = (bi == bj);
        const int gi0 = bi * TILE, gj0 = bj * TILE;

        // guard reuse of sNpos/sPos*/sRow/sCol against the previous tile's
        // flush reads (no-op contention on the first tile)
        __syncthreads();

        if (tid == 0) sNpos = 0u;
        if (tid < TILE) {
            sMagI[tid] = g_mag[gi0 + tid];
            sLabI[tid] = lab[gi0 + tid];
            sMagJ[tid] = g_mag[gj0 + tid];
            sLabJ[tid] = lab[gj0 + tid];
            sRow[tid] = 0.0f;
            sCol[tid] = 0.0f;
        }

        float acc[4][4][4];
#pragma unroll
        for (int mt = 0; mt < 4; mt++)
#pragma unroll
            for (int nt = 0; nt < 4; nt++)
#pragma unroll
                for (int r = 0; r < 4; r++) acc[mt][nt][r] = 0.0f;

        const __half* gA = g_Xh + (size_t)gi0 * KTOT;
        const __half* gB = g_Xh + (size_t)gj0 * KTOT;

        // ---- issue stage 0 ----
        {
            const uint32_t bufA = tbase, bufB = tbase + 16384u;
#pragma unroll
            for (int i = 0; i < 4; i++) {
                uint32_t off = swz(lrow[i] * 128 + lkc * 16);
                CP_ASYNC16(bufA + off, (const char*)(gA + (size_t)lrow[i] * KTOT) + lkc * 16);
            }
            if (!diag) {
#pragma unroll
                for (int i = 0; i < 4; i++) {
                    uint32_t off = swz(lrow[i] * 128 + lkc * 16);
                    CP_ASYNC16(bufB + off, (const char*)(gB + (size_t)lrow[i] * KTOT) + lkc * 16);
                }
            }
            CP_COMMIT();
        }

#pragma unroll 1
        for (int c = 0; c < NCHUNK; c++) {
            if (c + 1 < NCHUNK) {
                const uint32_t bufA = tbase + ((c + 1) & 1) * 32768u;
                const uint32_t bufB = bufA + 16384u;
                const char* srcA = (const char*)(gA + (c + 1) * KCH);
                const char* srcB = (const char*)(gB + (c + 1) * KCH);
#pragma unroll
                for (int i = 0; i < 4; i++) {
                    uint32_t off = swz(lrow[i] * 128 + lkc * 16);
                    CP_ASYNC16(bufA + off, srcA + (size_t)lrow[i] * KTOT * 2 + lkc * 16);
                }
                if (!diag) {
#pragma unroll
                    for (int i = 0; i < 4; i++) {
                        uint32_t off = swz(lrow[i] * 128 + lkc * 16);
                        CP_ASYNC16(bufB + off, srcB + (size_t)lrow[i] * KTOT * 2 + lkc * 16);
                    }
                }
                CP_COMMIT();
                CP_WAIT(1);
            } else {
                CP_WAIT(0);
            }
            __syncthreads();

            const uint32_t bA = tbase + (c & 1) * 32768u;
            const uint32_t bB = diag ? bA : bA + 16384u;

#pragma unroll
            for (int ks = 0; ks < 4; ks++) {
                uint32_t afr[4][4], bfr[4][2];
#pragma unroll
                for (int mt = 0; mt < 4; mt++) {
                    int row = m0w + mt * 16 + (lid & 15);
                    int ch = ks * 2 + (lid >> 4);
                    ldmatrix_x4(afr[mt][0], afr[mt][1], afr[mt][2], afr[mt][3],
                                bA + swz(row * 128 + ch * 16));
                }
#pragma unroll
                for (int nt = 0; nt < 4; nt++) {
                    int row = n0w + nt * 8 + (lid & 7);
                    int ch = ks * 2 + ((lid >> 3) & 1);
                    ldmatrix_x2(bfr[nt][0], bfr[nt][1], bB + swz(row * 128 + ch * 16));
                }
#pragma unroll
                for (int mt = 0; mt < 4; mt++)
#pragma unroll
                    for (int nt = 0; nt < 4; nt++)
                        mma_f16(acc[mt][nt], afr[mt], bfr[nt]);
            }
            __syncthreads();
        }

        // -------- epilogue from register fragments --------
        const int gID = lid >> 2;     // 0..7
        const int tig = lid & 3;      // 0..3

        float rs[4][2], cs[4][2];
#pragma unroll
        for (int x = 0; x < 4; x++) { rs[x][0] = rs[x][1] = 0.0f; cs[x][0] = cs[x][1] = 0.0f; }

#pragma unroll
        for (int mt = 0; mt < 4; mt++) {
            const int r0 = m0w + mt * 16 + gID;
            const int r1 = r0 + 8;
            const float mi0 = sMagI[r0], mi1 = sMagI[r1];
            const int li0 = sLabI[r0], li1 = sLabI[r1];
            const int gi_0 = gi0 + r0, gi_1 = gi0 + r1;
#pragma unroll
            for (int nt = 0; nt < 4; nt++) {
                const int c0 = n0w + nt * 8 + tig * 2;
                const int c1 = c0 + 1;
                const float mj0 = sMagJ[c0], mj1 = sMagJ[c1];
                const int lj0 = sLabJ[c0], lj1 = sLabJ[c1];
                const int gj_0 = gj0 + c0, gj_1 = gj0 + c1;

#define PROC(SIM, MI, LI, GI, MJ, LJ, GJ, RSUM, CSUM)                          \
                {                                                              \
                    float d2 = fmaxf((MI) + (MJ)-2.0f * (SIM), 0.0f);          \
                    float dist = sqrtf(d2);                                    \
                    if ((LI) != (LJ)) {                                        \
                        float e = (dist > 0.0f) ? __expf(MARGIN - dist) : 0.0f;\
                        RSUM += e;                                             \
                        CSUM += e;                                             \
                    } else if ((GI) < (GJ)) {                                  \
                        unsigned p = atomicAdd(&sNpos, 1u);                    \
                        unsigned key = ((unsigned)(GI) << 12) | (unsigned)(GJ);\
                        if (p < CAP) { sPosKey[p] = key; sPosDist[p] = dist; } \
                        else {                                                 \
                            unsigned q = atomicAdd(&g_npos, 1u);               \
                            g_pos_key[q] = key;                                \
                            g_pos_dist[q] = dist;                              \
                        }                                                      \
                    }                                                          \
                }
                PROC(acc[mt][nt][0], mi0, li0, gi_0, mj0, lj0, gj_0, rs[mt][0], cs[nt][0]);
                PROC(acc[mt][nt][1], mi0, li0, gi_0, mj1, lj1, gj_1, rs[mt][0], cs[nt][1]);
                PROC(acc[mt][nt][2], mi1, li1, gi_1, mj0, lj0, gj_0, rs[mt][1], cs[nt][0]);
                PROC(acc[mt][nt][3], mi1, li1, gi_1, mj1, lj1, gj_1, rs[mt][1], cs[nt][1]);
#undef PROC
            }
        }

        // row sums: reduce across lanes with same gID (xor low 2 bits)
#pragma unroll
        for (int mt = 0; mt < 4; mt++) {
            float v0 = rs[mt][0], v1 = rs[mt][1];
            v0 += __shfl_xor_sync(0xffffffffu, v0, 1);
            v0 += __shfl_xor_sync(0xffffffffu, v0, 2);
            v1 += __shfl_xor_sync(0xffffffffu, v1, 1);
            v1 += __shfl_xor_sync(0xffffffffu, v1, 2);
            if (tig == 0) {
                atomicAdd(&sRow[m0w + mt * 16 + gID], v0);
                atomicAdd(&sRow[m0w + mt * 16 + gID + 8], v1);
            }
        }
        // col sums: reduce across gID (xor bits 2..4); skip for diagonal tiles
        if (!diag) {
#pragma unroll
            for (int nt = 0; nt < 4; nt++) {
                float w0 = cs[nt][0], w1 = cs[nt][1];
                w0 += __shfl_xor_sync(0xffffffffu, w0, 4);
                w0 += __shfl_xor_sync(0xffffffffu, w0, 8);
                w0 += __shfl_xor_sync(0xffffffffu, w0, 16);
                w1 += __shfl_xor_sync(0xffffffffu, w1, 4);
                w1 += __shfl_xor_sync(0xffffffffu, w1, 8);
                w1 += __shfl_xor_sync(0xffffffffu, w1, 16);
                if (lid < 4) {
                    atomicAdd(&sCol[n0w + nt * 8 + lid * 2], w0);
                    atomicAdd(&sCol[n0w + nt * 8 + lid * 2 + 1], w1);
                }
            }
        }
        __syncthreads();

        if (tid < TILE) {
            atomicAdd(&g_rowneg[gi0 + tid], sRow[tid]);
            if (!diag) atomicAdd(&g_rowneg[gj0 + tid], sCol[tid]);
        }

        // flush buffered positive pairs with one reservation
        if (tid == 0) {
            unsigned np = sNpos < CAP ? sNpos : CAP;
            sBase = atomicAdd(&g_npos, np);
        }
        __syncthreads();
        const unsigned np = sNpos < CAP ? sNpos : CAP;
        for (unsigned k2 = tid; k2 < np; k2 += GTHREADS) {
            g_pos_key[sBase + k2] = sPosKey[k2];
            g_pos_dist[sBase + k2] = sPosDist[k2];
        }
    }
}

// ---------------- positive-pair loss + fused finalize (last block) ----------------
__global__ void k_loss2(float* __restrict__ out) {
    const unsigned total = g_npos;
    double lsum = 0.0;
    for (unsigned t = blockIdx.x * blockDim.x + threadIdx.x; t < total;
         t += gridDim.x * blockDim.x) {
        unsigned key = g_pos_key[t];
        float dist = g_pos_dist[t];
        int i = key >> 12;
        int j = key & 4095;
        float J = logf(g_rowneg[i] + g_rowneg[j]) + dist;
        float l = fmaxf(J, 0.0f);
        lsum += (double)l * (double)l;
    }
    __shared__ double sl[256];
    __shared__ unsigned sDone;
    int tid = threadIdx.x;
    sl[tid] = lsum;
    __syncthreads();
    for (int s = 128; s > 0; s >>= 1) {
        if (tid < s) sl[tid] += sl[tid + s];
        __syncthreads();
    }
    if (tid == 0) {
        if (sl[0] != 0.0) atomicAdd(&g_loss, sl[0]);
        __threadfence();
        sDone = atomicAdd(&g_ldone, 1u);
    }
    __syncthreads();
    if (sDone == gridDim.x - 1 && tid == 0) {
        __threadfence();
        out[0] = (float)(g_loss / (double)(2ULL * (unsigned long long)total));
    }
}

extern "C" void kernel_launch(void* const* d_in, const int* in_sizes, int n_in,
                              void* d_out, int out_size) {
    const float* X = (const float*)d_in[0];
    const int* lab = (const int*)d_in[1];
    float* out = (float*)d_out;

    cudaFuncSetAttribute(k_gemm, cudaFuncAttributeMaxDynamicSharedMemorySize, 66560);

    k_prep<<<N / 16, 256>>>(X);
    k_gemm<<<PGRID, GTHREADS, 66560>>>(lab);
    k_loss2<<<LGRID, 256>>>(out);
}

// round 15
// speedup vs baseline: 1.0072x; 1.0072x over previous
#include <cuda_runtime.h>
#include <cuda_fp16.h>
#include <math.h>
#include <stdint.h>

// Problem shape (fixed): inputs [4096,512] fp32, targets [4096] int32.
#define N 4096
#define D 512
#define MARGIN 1.0f

#define TILE 128
#define NTILES (N / TILE)                         // 32
#define NPAIR_TILES (NTILES * (NTILES + 1) / 2)   // 528
#define KTOT 512                                  // single-pass fp16
#define KCH 64                                    // fp16 per K-stage (128 B/row)
#define NCHUNK (KTOT / KCH)                       // 8
#define GTHREADS 256
#define CAP 1024                                  // smem positive-pair buffer per CTA
#define LGRID 256                                 // loss kernel grid

#define MAXPOS (N * (N - 1) / 2)

// ---------------- device scratch (no allocations allowed) ----------------
__device__ float g_mag[N];
__device__ float g_rowneg[N];
__device__ double g_loss;
__device__ unsigned g_npos;
__device__ unsigned g_ldone;
__device__ unsigned g_pos_key[MAXPOS];  // (i << 12) | j, i < j
__device__ float g_pos_dist[MAXPOS];
__device__ __half g_Xh[(size_t)N * KTOT];

// ---------------- PTX helpers (baseline PTX only: sm_80+ features) ----------------
__device__ __forceinline__ uint32_t smem_u32(const void* p) {
    uint32_t a;
    asm("{ .reg .u64 t; cvta.to.shared.u64 t, %1; cvt.u32.u64 %0, t; }"
        : "=r"(a) : "l"(p));
    return a;
}

#define CP_ASYNC16(dst, src) \
    asm volatile("cp.async.cg.shared.global [%0], [%1], 16;" \
                 :: "r"(dst), "l"(src) : "memory")
#define CP_COMMIT() asm volatile("cp.async.commit_group;" ::: "memory")
#define CP_WAIT(n)  asm volatile("cp.async.wait_group %0;" :: "n"(n) : "memory")

__device__ __forceinline__ void ldmatrix_x4(uint32_t& r0, uint32_t& r1,
                                            uint32_t& r2, uint32_t& r3,
                                            uint32_t addr) {
    asm volatile("ldmatrix.sync.aligned.m8n8.x4.shared.b16 {%0,%1,%2,%3}, [%4];"
                 : "=r"(r0), "=r"(r1), "=r"(r2), "=r"(r3) : "r"(addr));
}
__device__ __forceinline__ void ldmatrix_x2(uint32_t& r0, uint32_t& r1,
                                            uint32_t addr) {
    asm volatile("ldmatrix.sync.aligned.m8n8.x2.shared.b16 {%0,%1}, [%2];"
                 : "=r"(r0), "=r"(r1) : "r"(addr));
}
__device__ __forceinline__ void mma_f16(float* d, const uint32_t* a,
                                        const uint32_t* b) {
    asm volatile(
        "mma.sync.aligned.m16n8k16.row.col.f32.f16.f16.f32 "
        "{%0,%1,%2,%3}, {%4,%5,%6,%7}, {%8,%9}, {%0,%1,%2,%3};"
        : "+f"(d[0]), "+f"(d[1]), "+f"(d[2]), "+f"(d[3])
        : "r"(a[0]), "r"(a[1]), "r"(a[2]), "r"(a[3]), "r"(b[0]), "r"(b[1]));
}

__device__ __forceinline__ uint32_t swz(uint32_t off) {
    return off ^ ((off >> 3) & 0x70);
}

// ---------------- prep: mag + fp16 convert + counter init ----------------
// 512 blocks x 8 warps; each WARP independently owns one row (no block sync).
__global__ void k_prep(const float* __restrict__ X) {
    const int tid = threadIdx.x;      // 256
    const int wid = tid >> 5;
    const int lid = tid & 31;
    const int i = blockIdx.x * 8 + wid;

    const float4* xr = (const float4*)(X + (size_t)i * D);
    __half2* ph = (__half2*)(g_Xh + (size_t)i * KTOT);

    float s = 0.0f;
#pragma unroll
    for (int c = 0; c < 4; c++) {
        float4 v = xr[lid + c * 32];
        s += v.x * v.x + v.y * v.y + v.z * v.z + v.w * v.w;
        ph[(lid + c * 32) * 2 + 0] = __floats2half2_rn(v.x, v.y);
        ph[(lid + c * 32) * 2 + 1] = __floats2half2_rn(v.z, v.w);
    }
    for (int o = 16; o > 0; o >>= 1) s += __shfl_down_sync(0xffffffffu, s, o);
    if (lid == 0) {
        g_mag[i] = s;
        g_rowneg[i] = 0.0f;
        if (i == 0) { g_loss = 0.0; g_npos = 0u; g_ldone = 0u; }
    }
}

// ---------------- main pass: HMMA symmetric GEMM + fused epilogue ----------------
// 8 warps, each owns a 64x32 sub-tile (warp grid 2x4) via m16n8k16 fp16 MMA.
// Champion configuration (best measured: 66.5 us; re-measured 67.3/67.6).
__global__ void __launch_bounds__(GTHREADS, 2)
k_gemm(const int* __restrict__ lab) {
    __shared__ float sMagI[TILE], sMagJ[TILE];
    __shared__ int sLabI[TILE], sLabJ[TILE];
    __shared__ float sRow[TILE], sCol[TILE];
    __shared__ unsigned sPosKey[CAP];
    __shared__ float sPosDist[CAP];
    __shared__ unsigned sNpos, sBase;
    extern __shared__ char dsm[];

    const int tid = threadIdx.x;
    const int wid = tid >> 5;
    const int lid = tid & 31;
    const int wm = wid >> 2;      // warp row 0..1 -> m offset 0/64
    const int wn = wid & 3;       // warp col 0..3 -> n offset 0/32/64/96
    const int m0w = wm * 64;
    const int n0w = wn * 32;

    // decode upper-triangle tile (bi <= bj)
    int t = blockIdx.x, bi = 0;
    while (t >= NTILES - bi) { t -= NTILES - bi; bi++; }
    const int bj = bi + t;
    const bool diag = (bi == bj);
    const int gi0 = bi * TILE, gj0 = bj * TILE;

    // dynamic smem: [A0(16K) B0(16K) A1(16K) B1(16K)], 1024-aligned
    const uint32_t tbase = (smem_u32(dsm) + 1023u) & ~1023u;

    if (tid == 0) sNpos = 0u;
    if (tid < TILE) {
        sMagI[tid] = g_mag[gi0 + tid];
        sLabI[tid] = lab[gi0 + tid];
        sMagJ[tid] = g_mag[gj0 + tid];
        sLabJ[tid] = lab[gj0 + tid];
        sRow[tid] = 0.0f;
        sCol[tid] = 0.0f;
    }

    float acc[4][4][4];
#pragma unroll
    for (int mt = 0; mt < 4; mt++)
#pragma unroll
        for (int nt = 0; nt < 4; nt++)
#pragma unroll
            for (int r = 0; r < 4; r++) acc[mt][nt][r] = 0.0f;

    const __half* gA = g_Xh + (size_t)gi0 * KTOT;
    const __half* gB = g_Xh + (size_t)gj0 * KTOT;

    // per-thread load coords (4 x 16B chunks per tile per stage)
    const int lrow[4] = {(tid + 0) >> 3, (tid + 256) >> 3, (tid + 512) >> 3, (tid + 768) >> 3};
    const int lkc = tid & 7;

    // ---- issue stage 0 ----
    {
        const uint32_t bufA = tbase, bufB = tbase + 16384u;
#pragma unroll
        for (int i = 0; i < 4; i++) {
            uint32_t off = swz(lrow[i] * 128 + lkc * 16);
            CP_ASYNC16(bufA + off, (const char*)(gA + (size_t)lrow[i] * KTOT) + lkc * 16);
        }
        if (!diag) {
#pragma unroll
            for (int i = 0; i < 4; i++) {
                uint32_t off = swz(lrow[i] * 128 + lkc * 16);
                CP_ASYNC16(bufB + off, (const char*)(gB + (size_t)lrow[i] * KTOT) + lkc * 16);
            }
        }
        CP_COMMIT();
    }

#pragma unroll 1
    for (int c = 0; c < NCHUNK; c++) {
        if (c + 1 < NCHUNK) {
            const uint32_t bufA = tbase + ((c + 1) & 1) * 32768u;
            const uint32_t bufB = bufA + 16384u;
            const char* srcA = (const char*)(gA + (c + 1) * KCH);
            const char* srcB = (const char*)(gB + (c + 1) * KCH);
#pragma unroll
            for (int i = 0; i < 4; i++) {
                uint32_t off = swz(lrow[i] * 128 + lkc * 16);
                CP_ASYNC16(bufA + off, srcA + (size_t)lrow[i] * KTOT * 2 + lkc * 16);
            }
            if (!diag) {
#pragma unroll
                for (int i = 0; i < 4; i++) {
                    uint32_t off = swz(lrow[i] * 128 + lkc * 16);
                    CP_ASYNC16(bufB + off, srcB + (size_t)lrow[i] * KTOT * 2 + lkc * 16);
                }
            }
            CP_COMMIT();
            CP_WAIT(1);
        } else {
            CP_WAIT(0);
        }
        __syncthreads();

        const uint32_t bA = tbase + (c & 1) * 32768u;
        const uint32_t bB = diag ? bA : bA + 16384u;

#pragma unroll
        for (int ks = 0; ks < 4; ks++) {
            uint32_t afr[4][4], bfr[4][2];
#pragma unroll
            for (int mt = 0; mt < 4; mt++) {
                int row = m0w + mt * 16 + (lid & 15);
                int ch = ks * 2 + (lid >> 4);
                ldmatrix_x4(afr[mt][0], afr[mt][1], afr[mt][2], afr[mt][3],
                            bA + swz(row * 128 + ch * 16));
            }
#pragma unroll
            for (int nt = 0; nt < 4; nt++) {
                int row = n0w + nt * 8 + (lid & 7);
                int ch = ks * 2 + ((lid >> 3) & 1);
                ldmatrix_x2(bfr[nt][0], bfr[nt][1], bB + swz(row * 128 + ch * 16));
            }
#pragma unroll
            for (int mt = 0; mt < 4; mt++)
#pragma unroll
                for (int nt = 0; nt < 4; nt++)
                    mma_f16(acc[mt][nt], afr[mt], bfr[nt]);
        }
        __syncthreads();
    }

    // -------- epilogue from register fragments --------
    const int gID = lid >> 2;     // 0..7
    const int tig = lid & 3;      // 0..3

    float rs[4][2], cs[4][2];
#pragma unroll
    for (int x = 0; x < 4; x++) { rs[x][0] = rs[x][1] = 0.0f; cs[x][0] = cs[x][1] = 0.0f; }

#pragma unroll
    for (int mt = 0; mt < 4; mt++) {
        const int r0 = m0w + mt * 16 + gID;
        const int r1 = r0 + 8;
        const float mi0 = sMagI[r0], mi1 = sMagI[r1];
        const int li0 = sLabI[r0], li1 = sLabI[r1];
        const int gi_0 = gi0 + r0, gi_1 = gi0 + r1;
#pragma unroll
        for (int nt = 0; nt < 4; nt++) {
            const int c0 = n0w + nt * 8 + tig * 2;
            const int c1 = c0 + 1;
            const float mj0 = sMagJ[c0], mj1 = sMagJ[c1];
            const int lj0 = sLabJ[c0], lj1 = sLabJ[c1];
            const int gj_0 = gj0 + c0, gj_1 = gj0 + c1;

#define PROC(SIM, MI, LI, GI, MJ, LJ, GJ, RSUM, CSUM)                          \
            {                                                                  \
                float d2 = fmaxf((MI) + (MJ)-2.0f * (SIM), 0.0f);              \
                float dist = sqrtf(d2);                                        \
                if ((LI) != (LJ)) {                                            \
                    float e = (dist > 0.0f) ? __expf(MARGIN - dist) : 0.0f;    \
                    RSUM += e;                                                 \
                    CSUM += e;                                                 \
                } else if ((GI) < (GJ)) {                                      \
                    unsigned p = atomicAdd(&sNpos, 1u);                        \
                    unsigned key = ((unsigned)(GI) << 12) | (unsigned)(GJ);    \
                    if (p < CAP) { sPosKey[p] = key; sPosDist[p] = dist; }     \
                    else {                                                     \
                        unsigned q = atomicAdd(&g_npos, 1u);                   \
                        g_pos_key[q] = key;                                    \
                        g_pos_dist[q] = dist;                                  \
                    }                                                          \
                }                                                              \
            }
            PROC(acc[mt][nt][0], mi0, li0, gi_0, mj0, lj0, gj_0, rs[mt][0], cs[nt][0]);
            PROC(acc[mt][nt][1], mi0, li0, gi_0, mj1, lj1, gj_1, rs[mt][0], cs[nt][1]);
            PROC(acc[mt][nt][2], mi1, li1, gi_1, mj0, lj0, gj_0, rs[mt][1], cs[nt][0]);
            PROC(acc[mt][nt][3], mi1, li1, gi_1, mj1, lj1, gj_1, rs[mt][1], cs[nt][1]);
#undef PROC
        }
    }

    // row sums: reduce across lanes with same gID (xor low 2 bits)
#pragma unroll
    for (int mt = 0; mt < 4; mt++) {
        float v0 = rs[mt][0], v1 = rs[mt][1];
        v0 += __shfl_xor_sync(0xffffffffu, v0, 1);
        v0 += __shfl_xor_sync(0xffffffffu, v0, 2);
        v1 += __shfl_xor_sync(0xffffffffu, v1, 1);
        v1 += __shfl_xor_sync(0xffffffffu, v1, 2);
        if (tig == 0) {
            atomicAdd(&sRow[m0w + mt * 16 + gID], v0);
            atomicAdd(&sRow[m0w + mt * 16 + gID + 8], v1);
        }
    }
    // col sums: reduce across gID (xor bits 2..4); skip for diagonal tiles
    if (!diag) {
#pragma unroll
        for (int nt = 0; nt < 4; nt++) {
            float w0 = cs[nt][0], w1 = cs[nt][1];
            w0 += __shfl_xor_sync(0xffffffffu, w0, 4);
            w0 += __shfl_xor_sync(0xffffffffu, w0, 8);
            w0 += __shfl_xor_sync(0xffffffffu, w0, 16);
            w1 += __shfl_xor_sync(0xffffffffu, w1, 4);
            w1 += __shfl_xor_sync(0xffffffffu, w1, 8);
            w1 += __shfl_xor_sync(0xffffffffu, w1, 16);
            if (lid < 4) {
                atomicAdd(&sCol[n0w + nt * 8 + lid * 2], w0);
                atomicAdd(&sCol[n0w + nt * 8 + lid * 2 + 1], w1);
            }
        }
    }
    __syncthreads();

    if (tid < TILE) {
        atomicAdd(&g_rowneg[gi0 + tid], sRow[tid]);
        if (!diag) atomicAdd(&g_rowneg[gj0 + tid], sCol[tid]);
    }

    // flush buffered positive pairs with one reservation
    if (tid == 0) {
        unsigned np = sNpos < CAP ? sNpos : CAP;
        sBase = atomicAdd(&g_npos, np);
    }
    __syncthreads();
    const unsigned np = sNpos < CAP ? sNpos : CAP;
    for (unsigned k2 = tid; k2 < np; k2 += GTHREADS) {
        g_pos_key[sBase + k2] = sPosKey[k2];
        g_pos_dist[sBase + k2] = sPosDist[k2];
    }
}

// ---------------- positive-pair loss + fused finalize (last block) ----------------
__global__ void k_loss2(float* __restrict__ out) {
    const unsigned total = g_npos;
    double lsum = 0.0;
    for (unsigned t = blockIdx.x * blockDim.x + threadIdx.x; t < total;
         t += gridDim.x * blockDim.x) {
        unsigned key = g_pos_key[t];
        float dist = g_pos_dist[t];
        int i = key >> 12;
        int j = key & 4095;
        float J = logf(g_rowneg[i] + g_rowneg[j]) + dist;
        float l = fmaxf(J, 0.0f);
        lsum += (double)l * (double)l;
    }
    __shared__ double sl[256];
    __shared__ unsigned sDone;
    int tid = threadIdx.x;
    sl[tid] = lsum;
    __syncthreads();
    for (int s = 128; s > 0; s >>= 1) {
        if (tid < s) sl[tid] += sl[tid + s];
        __syncthreads();
    }
    if (tid == 0) {
        if (sl[0] != 0.0) atomicAdd(&g_loss, sl[0]);
        __threadfence();
        sDone = atomicAdd(&g_ldone, 1u);
    }
    __syncthreads();
    if (sDone == gridDim.x - 1 && tid == 0) {
        __threadfence();
        out[0] = (float)(g_loss / (double)(2ULL * (unsigned long long)total));
    }
}

extern "C" void kernel_launch(void* const* d_in, const int* in_sizes, int n_in,
                              void* d_out, int out_size) {
    const float* X = (const float*)d_in[0];
    const int* lab = (const int*)d_in[1];
    float* out = (float*)d_out;

    cudaFuncSetAttribute(k_gemm, cudaFuncAttributeMaxDynamicSharedMemorySize, 66560);

    k_prep<<<N / 8, 256>>>(X);
    k_gemm<<<NPAIR_TILES, GTHREADS, 66560>>>(lab);
    k_loss2<<<LGRID, 256>>>(out);
}

// round 16
// speedup vs baseline: 1.0640x; 1.0564x over previous
#include <cuda_runtime.h>
#include <cuda_fp16.h>
#include <math.h>
#include <stdint.h>

// Problem shape (fixed): inputs [4096,512] fp32, targets [4096] int32.
#define N 4096
#define D 512
#define MARGIN 1.0f

#define TILE 128
#define NTILES (N / TILE)                         // 32
#define NPAIR_TILES (NTILES * (NTILES + 1) / 2)   // 528
#define KTOT 512                                  // single-pass fp16
#define KCH 64                                    // fp16 per K-stage (128 B/row)
#define NCHUNK (KTOT / KCH)                       // 8
#define GTHREADS 256
#define CAP 1024                                  // smem positive-pair buffer per CTA
#define LGRID 256                                 // loss kernel grid

#define MAXPOS (N * (N - 1) / 2)

// ---------------- device scratch (no allocations allowed) ----------------
__device__ float g_mag[N];
__device__ float g_rowneg[N];
__device__ double g_loss;
__device__ unsigned g_npos;
__device__ unsigned g_ldone;
__device__ unsigned g_pos_key[MAXPOS];  // (i << 12) | j, i < j
__device__ float g_pos_dist[MAXPOS];
__device__ __half g_Xh[(size_t)N * KTOT];

// ---------------- PTX helpers (baseline PTX only: sm_80+ features) ----------------
__device__ __forceinline__ uint32_t smem_u32(const void* p) {
    uint32_t a;
    asm("{ .reg .u64 t; cvta.to.shared.u64 t, %1; cvt.u32.u64 %0, t; }"
        : "=r"(a) : "l"(p));
    return a;
}

#define CP_ASYNC16(dst, src) \
    asm volatile("cp.async.cg.shared.global [%0], [%1], 16;" \
                 :: "r"(dst), "l"(src) : "memory")
#define CP_COMMIT() asm volatile("cp.async.commit_group;" ::: "memory")
#define CP_WAIT(n)  asm volatile("cp.async.wait_group %0;" :: "n"(n) : "memory")

__device__ __forceinline__ void ldmatrix_x4(uint32_t& r0, uint32_t& r1,
                                            uint32_t& r2, uint32_t& r3,
                                            uint32_t addr) {
    asm volatile("ldmatrix.sync.aligned.m8n8.x4.shared.b16 {%0,%1,%2,%3}, [%4];"
                 : "=r"(r0), "=r"(r1), "=r"(r2), "=r"(r3) : "r"(addr));
}
__device__ __forceinline__ void ldmatrix_x2(uint32_t& r0, uint32_t& r1,
                                            uint32_t addr) {
    asm volatile("ldmatrix.sync.aligned.m8n8.x2.shared.b16 {%0,%1}, [%2];"
                 : "=r"(r0), "=r"(r1) : "r"(addr));
}
__device__ __forceinline__ void mma_f16(float* d, const uint32_t* a,
                                        const uint32_t* b) {
    asm volatile(
        "mma.sync.aligned.m16n8k16.row.col.f32.f16.f16.f32 "
        "{%0,%1,%2,%3}, {%4,%5,%6,%7}, {%8,%9}, {%0,%1,%2,%3};"
        : "+f"(d[0]), "+f"(d[1]), "+f"(d[2]), "+f"(d[3])
        : "r"(a[0]), "r"(a[1]), "r"(a[2]), "r"(a[3]), "r"(b[0]), "r"(b[1]));
}

__device__ __forceinline__ uint32_t swz(uint32_t off) {
    return off ^ ((off >> 3) & 0x70);
}

// Fast sqrt via MUFU.RSQ: one MUFU + one FMUL instead of the IEEE sqrtf
// sequence (if fast-math is off in the harness). Guarded against d2 == 0
// (0 * inf = NaN). 2-ulp accuracy — far inside the 1e-3 gate.
__device__ __forceinline__ float fast_dist(float d2) {
    return (d2 > 0.0f) ? d2 * rsqrtf(d2) : 0.0f;
}

// ---------------- prep: mag + fp16 convert + counter init ----------------
// 512 blocks x 8 warps; each WARP independently owns one row (no block sync).
__global__ void k_prep(const float* __restrict__ X) {
    const int tid = threadIdx.x;      // 256
    const int wid = tid >> 5;
    const int lid = tid & 31;
    const int i = blockIdx.x * 8 + wid;

    const float4* xr = (const float4*)(X + (size_t)i * D);
    __half2* ph = (__half2*)(g_Xh + (size_t)i * KTOT);

    float s = 0.0f;
#pragma unroll
    for (int c = 0; c < 4; c++) {
        float4 v = xr[lid + c * 32];
        s += v.x * v.x + v.y * v.y + v.z * v.z + v.w * v.w;
        ph[(lid + c * 32) * 2 + 0] = __floats2half2_rn(v.x, v.y);
        ph[(lid + c * 32) * 2 + 1] = __floats2half2_rn(v.z, v.w);
    }
    for (int o = 16; o > 0; o >>= 1) s += __shfl_down_sync(0xffffffffu, s, o);
    if (lid == 0) {
        g_mag[i] = s;
        g_rowneg[i] = 0.0f;
        if (i == 0) { g_loss = 0.0; g_npos = 0u; g_ldone = 0u; }
    }
}

// ---------------- main pass: HMMA symmetric GEMM + fused epilogue ----------------
// 8 warps, each owns a 64x32 sub-tile (warp grid 2x4) via m16n8k16 fp16 MMA.
// Champion configuration; ONLY change vs champion: sqrtf -> fast_dist (MUFU.RSQ).
__global__ void __launch_bounds__(GTHREADS, 2)
k_gemm(const int* __restrict__ lab) {
    __shared__ float sMagI[TILE], sMagJ[TILE];
    __shared__ int sLabI[TILE], sLabJ[TILE];
    __shared__ float sRow[TILE], sCol[TILE];
    __shared__ unsigned sPosKey[CAP];
    __shared__ float sPosDist[CAP];
    __shared__ unsigned sNpos, sBase;
    extern __shared__ char dsm[];

    const int tid = threadIdx.x;
    const int wid = tid >> 5;
    const int lid = tid & 31;
    const int wm = wid >> 2;      // warp row 0..1 -> m offset 0/64
    const int wn = wid & 3;       // warp col 0..3 -> n offset 0/32/64/96
    const int m0w = wm * 64;
    const int n0w = wn * 32;

    // decode upper-triangle tile (bi <= bj)
    int t = blockIdx.x, bi = 0;
    while (t >= NTILES - bi) { t -= NTILES - bi; bi++; }
    const int bj = bi + t;
    const bool diag = (bi == bj);
    const int gi0 = bi * TILE, gj0 = bj * TILE;

    // dynamic smem: [A0(16K) B0(16K) A1(16K) B1(16K)], 1024-aligned
    const uint32_t tbase = (smem_u32(dsm) + 1023u) & ~1023u;

    if (tid == 0) sNpos = 0u;
    if (tid < TILE) {
        sMagI[tid] = g_mag[gi0 + tid];
        sLabI[tid] = lab[gi0 + tid];
        sMagJ[tid] = g_mag[gj0 + tid];
        sLabJ[tid] = lab[gj0 + tid];
        sRow[tid] = 0.0f;
        sCol[tid] = 0.0f;
    }

    float acc[4][4][4];
#pragma unroll
    for (int mt = 0; mt < 4; mt++)
#pragma unroll
        for (int nt = 0; nt < 4; nt++)
#pragma unroll
            for (int r = 0; r < 4; r++) acc[mt][nt][r] = 0.0f;

    const __half* gA = g_Xh + (size_t)gi0 * KTOT;
    const __half* gB = g_Xh + (size_t)gj0 * KTOT;

    // per-thread load coords (4 x 16B chunks per tile per stage)
    const int lrow[4] = {(tid + 0) >> 3, (tid + 256) >> 3, (tid + 512) >> 3, (tid + 768) >> 3};
    const int lkc = tid & 7;

    // ---- issue stage 0 ----
    {
        const uint32_t bufA = tbase, bufB = tbase + 16384u;
#pragma unroll
        for (int i = 0; i < 4; i++) {
            uint32_t off = swz(lrow[i] * 128 + lkc * 16);
            CP_ASYNC16(bufA + off, (const char*)(gA + (size_t)lrow[i] * KTOT) + lkc * 16);
        }
        if (!diag) {
#pragma unroll
            for (int i = 0; i < 4; i++) {
                uint32_t off = swz(lrow[i] * 128 + lkc * 16);
                CP_ASYNC16(bufB + off, (const char*)(gB + (size_t)lrow[i] * KTOT) + lkc * 16);
            }
        }
        CP_COMMIT();
    }

#pragma unroll 1
    for (int c = 0; c < NCHUNK; c++) {
        if (c + 1 < NCHUNK) {
            const uint32_t bufA = tbase + ((c + 1) & 1) * 32768u;
            const uint32_t bufB = bufA + 16384u;
            const char* srcA = (const char*)(gA + (c + 1) * KCH);
            const char* srcB = (const char*)(gB + (c + 1) * KCH);
#pragma unroll
            for (int i = 0; i < 4; i++) {
                uint32_t off = swz(lrow[i] * 128 + lkc * 16);
                CP_ASYNC16(bufA + off, srcA + (size_t)lrow[i] * KTOT * 2 + lkc * 16);
            }
            if (!diag) {
#pragma unroll
                for (int i = 0; i < 4; i++) {
                    uint32_t off = swz(lrow[i] * 128 + lkc * 16);
                    CP_ASYNC16(bufB + off, srcB + (size_t)lrow[i] * KTOT * 2 + lkc * 16);
                }
            }
            CP_COMMIT();
            CP_WAIT(1);
        } else {
            CP_WAIT(0);
        }
        __syncthreads();

        const uint32_t bA = tbase + (c & 1) * 32768u;
        const uint32_t bB = diag ? bA : bA + 16384u;

#pragma unroll
        for (int ks = 0; ks < 4; ks++) {
            uint32_t afr[4][4], bfr[4][2];
#pragma unroll
            for (int mt = 0; mt < 4; mt++) {
                int row = m0w + mt * 16 + (lid & 15);
                int ch = ks * 2 + (lid >> 4);
                ldmatrix_x4(afr[mt][0], afr[mt][1], afr[mt][2], afr[mt][3],
                            bA + swz(row * 128 + ch * 16));
            }
#pragma unroll
            for (int nt = 0; nt < 4; nt++) {
                int row = n0w + nt * 8 + (lid & 7);
                int ch = ks * 2 + ((lid >> 3) & 1);
                ldmatrix_x2(bfr[nt][0], bfr[nt][1], bB + swz(row * 128 + ch * 16));
            }
#pragma unroll
            for (int mt = 0; mt < 4; mt++)
#pragma unroll
                for (int nt = 0; nt < 4; nt++)
                    mma_f16(acc[mt][nt], afr[mt], bfr[nt]);
        }
        __syncthreads();
    }

    // -------- epilogue from register fragments --------
    const int gID = lid >> 2;     // 0..7
    const int tig = lid & 3;      // 0..3

    float rs[4][2], cs[4][2];
#pragma unroll
    for (int x = 0; x < 4; x++) { rs[x][0] = rs[x][1] = 0.0f; cs[x][0] = cs[x][1] = 0.0f; }

#pragma unroll
    for (int mt = 0; mt < 4; mt++) {
        const int r0 = m0w + mt * 16 + gID;
        const int r1 = r0 + 8;
        const float mi0 = sMagI[r0], mi1 = sMagI[r1];
        const int li0 = sLabI[r0], li1 = sLabI[r1];
        const int gi_0 = gi0 + r0, gi_1 = gi0 + r1;
#pragma unroll
        for (int nt = 0; nt < 4; nt++) {
            const int c0 = n0w + nt * 8 + tig * 2;
            const int c1 = c0 + 1;
            const float mj0 = sMagJ[c0], mj1 = sMagJ[c1];
            const int lj0 = sLabJ[c0], lj1 = sLabJ[c1];
            const int gj_0 = gj0 + c0, gj_1 = gj0 + c1;

#define PROC(SIM, MI, LI, GI, MJ, LJ, GJ, RSUM, CSUM)                          \
            {                                                                  \
                float d2 = fmaxf((MI) + (MJ)-2.0f * (SIM), 0.0f);              \
                float dist = fast_dist(d2);                                    \
                if ((LI) != (LJ)) {                                            \
                    float e = (dist > 0.0f) ? __expf(MARGIN - dist) : 0.0f;    \
                    RSUM += e;                                                 \
                    CSUM += e;                                                 \
                } else if ((GI) < (GJ)) {                                      \
                    unsigned p = atomicAdd(&sNpos, 1u);                        \
                    unsigned key = ((unsigned)(GI) << 12) | (unsigned)(GJ);    \
                    if (p < CAP) { sPosKey[p] = key; sPosDist[p] = dist; }     \
                    else {                                                     \
                        unsigned q = atomicAdd(&g_npos, 1u);                   \
                        g_pos_key[q] = key;                                    \
                        g_pos_dist[q] = dist;                                  \
                    }                                                          \
                }                                                              \
            }
            PROC(acc[mt][nt][0], mi0, li0, gi_0, mj0, lj0, gj_0, rs[mt][0], cs[nt][0]);
            PROC(acc[mt][nt][1], mi0, li0, gi_0, mj1, lj1, gj_1, rs[mt][0], cs[nt][1]);
            PROC(acc[mt][nt][2], mi1, li1, gi_1, mj0, lj0, gj_0, rs[mt][1], cs[nt][0]);
            PROC(acc[mt][nt][3], mi1, li1, gi_1, mj1, lj1, gj_1, rs[mt][1], cs[nt][1]);
#undef PROC
        }
    }

    // row sums: reduce across lanes with same gID (xor low 2 bits)
#pragma unroll
    for (int mt = 0; mt < 4; mt++) {
        float v0 = rs[mt][0], v1 = rs[mt][1];
        v0 += __shfl_xor_sync(0xffffffffu, v0, 1);
        v0 += __shfl_xor_sync(0xffffffffu, v0, 2);
        v1 += __shfl_xor_sync(0xffffffffu, v1, 1);
        v1 += __shfl_xor_sync(0xffffffffu, v1, 2);
        if (tig == 0) {
            atomicAdd(&sRow[m0w + mt * 16 + gID], v0);
            atomicAdd(&sRow[m0w + mt * 16 + gID + 8], v1);
        }
    }
    // col sums: reduce across gID (xor bits 2..4); skip for diagonal tiles
    if (!diag) {
#pragma unroll
        for (int nt = 0; nt < 4; nt++) {
            float w0 = cs[nt][0], w1 = cs[nt][1];
            w0 += __shfl_xor_sync(0xffffffffu, w0, 4);
            w0 += __shfl_xor_sync(0xffffffffu, w0, 8);
            w0 += __shfl_xor_sync(0xffffffffu, w0, 16);
            w1 += __shfl_xor_sync(0xffffffffu, w1, 4);
            w1 += __shfl_xor_sync(0xffffffffu, w1, 8);
            w1 += __shfl_xor_sync(0xffffffffu, w1, 16);
            if (lid < 4) {
                atomicAdd(&sCol[n0w + nt * 8 + lid * 2], w0);
                atomicAdd(&sCol[n0w + nt * 8 + lid * 2 + 1], w1);
            }
        }
    }
    __syncthreads();

    if (tid < TILE) {
        atomicAdd(&g_rowneg[gi0 + tid], sRow[tid]);
        if (!diag) atomicAdd(&g_rowneg[gj0 + tid], sCol[tid]);
    }

    // flush buffered positive pairs with one reservation
    if (tid == 0) {
        unsigned np = sNpos < CAP ? sNpos : CAP;
        sBase = atomicAdd(&g_npos, np);
    }
    __syncthreads();
    const unsigned np = sNpos < CAP ? sNpos : CAP;
    for (unsigned k2 = tid; k2 < np; k2 += GTHREADS) {
        g_pos_key[sBase + k2] = sPosKey[k2];
        g_pos_dist[sBase + k2] = sPosDist[k2];
    }
}

// ---------------- positive-pair loss + fused finalize (last block) ----------------
__global__ void k_loss2(float* __restrict__ out) {
    const unsigned total = g_npos;
    double lsum = 0.0;
    for (unsigned t = blockIdx.x * blockDim.x + threadIdx.x; t < total;
         t += gridDim.x * blockDim.x) {
        unsigned key = g_pos_key[t];
        float dist = g_pos_dist[t];
        int i = key >> 12;
        int j = key & 4095;
        float J = logf(g_rowneg[i] + g_rowneg[j]) + dist;
        float l = fmaxf(J, 0.0f);
        lsum += (double)l * (double)l;
    }
    __shared__ double sl[256];
    __shared__ unsigned sDone;
    int tid = threadIdx.x;
    sl[tid] = lsum;
    __syncthreads();
    for (int s = 128; s > 0; s >>= 1) {
        if (tid < s) sl[tid] += sl[tid + s];
        __syncthreads();
    }
    if (tid == 0) {
        if (sl[0] != 0.0) atomicAdd(&g_loss, sl[0]);
        __threadfence();
        sDone = atomicAdd(&g_ldone, 1u);
    }
    __syncthreads();
    if (sDone == gridDim.x - 1 && tid == 0) {
        __threadfence();
        out[0] = (float)(g_loss / (double)(2ULL * (unsigned long long)total));
    }
}

extern "C" void kernel_launch(void* const* d_in, const int* in_sizes, int n_in,
                              void* d_out, int out_size) {
    const float* X = (const float*)d_in[0];
    const int* lab = (const int*)d_in[1];
    float* out = (float*)d_out;

    cudaFuncSetAttribute(k_gemm, cudaFuncAttributeMaxDynamicSharedMemorySize, 66560);

    k_prep<<<N / 8, 256>>>(X);
    k_gemm<<<NPAIR_TILES, GTHREADS, 66560>>>(lab);
    k_loss2<<<LGRID, 256>>>(out);
}

// round 17
// speedup vs baseline: 1.0915x; 1.0258x over previous
#include <cuda_runtime.h>
#include <cuda_fp16.h>
#include <math.h>
#include <stdint.h>

// Problem shape (fixed): inputs [4096,512] fp32, targets [4096] int32.
#define N 4096
#define D 512
#define MARGIN 1.0f

#define TILE 128
#define NTILES (N / TILE)                         // 32
#define NPAIR_TILES (NTILES * (NTILES + 1) / 2)   // 528
#define KTOT 512                                  // single-pass fp16
#define KCH 64                                    // fp16 per K-stage (128 B/row)
#define NCHUNK (KTOT / KCH)                       // 8
#define GTHREADS 256
#define CAP 1024                                  // smem positive-pair buffer per CTA
#define LGRID 256                                 // loss kernel grid

#define MAXPOS (N * (N - 1) / 2)

// ---------------- device scratch (no allocations allowed) ----------------
__device__ float g_mag[N];
__device__ float g_rowneg[N];
__device__ double g_loss;
__device__ unsigned g_npos;
__device__ unsigned g_ldone;
__device__ unsigned g_pos_key[MAXPOS];  // (i << 12) | j, i < j
__device__ float g_pos_dist[MAXPOS];
__device__ __half g_Xh[(size_t)N * KTOT];

// ---------------- PTX helpers (baseline PTX only: sm_80+ features) ----------------
__device__ __forceinline__ uint32_t smem_u32(const void* p) {
    uint32_t a;
    asm("{ .reg .u64 t; cvta.to.shared.u64 t, %1; cvt.u32.u64 %0, t; }"
        : "=r"(a) : "l"(p));
    return a;
}

#define CP_ASYNC16(dst, src) \
    asm volatile("cp.async.cg.shared.global [%0], [%1], 16;" \
                 :: "r"(dst), "l"(src) : "memory")
#define CP_COMMIT() asm volatile("cp.async.commit_group;" ::: "memory")
#define CP_WAIT(n)  asm volatile("cp.async.wait_group %0;" :: "n"(n) : "memory")

__device__ __forceinline__ void ldmatrix_x4(uint32_t& r0, uint32_t& r1,
                                            uint32_t& r2, uint32_t& r3,
                                            uint32_t addr) {
    asm volatile("ldmatrix.sync.aligned.m8n8.x4.shared.b16 {%0,%1,%2,%3}, [%4];"
                 : "=r"(r0), "=r"(r1), "=r"(r2), "=r"(r3) : "r"(addr));
}
__device__ __forceinline__ void ldmatrix_x2(uint32_t& r0, uint32_t& r1,
                                            uint32_t addr) {
    asm volatile("ldmatrix.sync.aligned.m8n8.x2.shared.b16 {%0,%1}, [%2];"
                 : "=r"(r0), "=r"(r1) : "r"(addr));
}
__device__ __forceinline__ void mma_f16(float* d, const uint32_t* a,
                                        const uint32_t* b) {
    asm volatile(
        "mma.sync.aligned.m16n8k16.row.col.f32.f16.f16.f32 "
        "{%0,%1,%2,%3}, {%4,%5,%6,%7}, {%8,%9}, {%0,%1,%2,%3};"
        : "+f"(d[0]), "+f"(d[1]), "+f"(d[2]), "+f"(d[3])
        : "r"(a[0]), "r"(a[1]), "r"(a[2]), "r"(a[3]), "r"(b[0]), "r"(b[1]));
}

__device__ __forceinline__ uint32_t swz(uint32_t off) {
    return off ^ ((off >> 3) & 0x70);
}

// Single-MUFU approximate sqrt (sqrt.approx.f32 -> MUFU.SQRT). Maps 0 -> 0
// natively, so no guard select or extra FMUL is needed (vs rsqrt*x).
// ~2-ulp accuracy — far inside the 1e-3 gate (validated in R16).
__device__ __forceinline__ float fast_dist(float d2) {
    float r;
    asm("sqrt.approx.f32 %0, %1;" : "=f"(r) : "f"(d2));
    return r;
}

// ---------------- prep: mag + fp16 convert + counter init ----------------
// 512 blocks x 8 warps; each WARP independently owns one row (no block sync).
__global__ void k_prep(const float* __restrict__ X) {
    const int tid = threadIdx.x;      // 256
    const int wid = tid >> 5;
    const int lid = tid & 31;
    const int i = blockIdx.x * 8 + wid;

    const float4* xr = (const float4*)(X + (size_t)i * D);
    __half2* ph = (__half2*)(g_Xh + (size_t)i * KTOT);

    float s = 0.0f;
#pragma unroll
    for (int c = 0; c < 4; c++) {
        float4 v = xr[lid + c * 32];
        s += v.x * v.x + v.y * v.y + v.z * v.z + v.w * v.w;
        ph[(lid + c * 32) * 2 + 0] = __floats2half2_rn(v.x, v.y);
        ph[(lid + c * 32) * 2 + 1] = __floats2half2_rn(v.z, v.w);
    }
    for (int o = 16; o > 0; o >>= 1) s += __shfl_down_sync(0xffffffffu, s, o);
    if (lid == 0) {
        g_mag[i] = s;
        g_rowneg[i] = 0.0f;
        if (i == 0) { g_loss = 0.0; g_npos = 0u; g_ldone = 0u; }
    }
}

// ---------------- main pass: HMMA symmetric GEMM + fused epilogue ----------------
// 8 warps, each owns a 64x32 sub-tile (warp grid 2x4) via m16n8k16 fp16 MMA.
// Champion configuration; ONLY change vs R16 champion: fast_dist now a single
// sqrt.approx (drops the guard select + FMUL per element).
__global__ void __launch_bounds__(GTHREADS, 2)
k_gemm(const int* __restrict__ lab) {
    __shared__ float sMagI[TILE], sMagJ[TILE];
    __shared__ int sLabI[TILE], sLabJ[TILE];
    __shared__ float sRow[TILE], sCol[TILE];
    __shared__ unsigned sPosKey[CAP];
    __shared__ float sPosDist[CAP];
    __shared__ unsigned sNpos, sBase;
    extern __shared__ char dsm[];

    const int tid = threadIdx.x;
    const int wid = tid >> 5;
    const int lid = tid & 31;
    const int wm = wid >> 2;      // warp row 0..1 -> m offset 0/64
    const int wn = wid & 3;       // warp col 0..3 -> n offset 0/32/64/96
    const int m0w = wm * 64;
    const int n0w = wn * 32;

    // decode upper-triangle tile (bi <= bj)
    int t = blockIdx.x, bi = 0;
    while (t >= NTILES - bi) { t -= NTILES - bi; bi++; }
    const int bj = bi + t;
    const bool diag = (bi == bj);
    const int gi0 = bi * TILE, gj0 = bj * TILE;

    // dynamic smem: [A0(16K) B0(16K) A1(16K) B1(16K)], 1024-aligned
    const uint32_t tbase = (smem_u32(dsm) + 1023u) & ~1023u;

    if (tid == 0) sNpos = 0u;
    if (tid < TILE) {
        sMagI[tid] = g_mag[gi0 + tid];
        sLabI[tid] = lab[gi0 + tid];
        sMagJ[tid] = g_mag[gj0 + tid];
        sLabJ[tid] = lab[gj0 + tid];
        sRow[tid] = 0.0f;
        sCol[tid] = 0.0f;
    }

    float acc[4][4][4];
#pragma unroll
    for (int mt = 0; mt < 4; mt++)
#pragma unroll
        for (int nt = 0; nt < 4; nt++)
#pragma unroll
            for (int r = 0; r < 4; r++) acc[mt][nt][r] = 0.0f;

    const __half* gA = g_Xh + (size_t)gi0 * KTOT;
    const __half* gB = g_Xh + (size_t)gj0 * KTOT;

    // per-thread load coords (4 x 16B chunks per tile per stage)
    const int lrow[4] = {(tid + 0) >> 3, (tid + 256) >> 3, (tid + 512) >> 3, (tid + 768) >> 3};
    const int lkc = tid & 7;

    // ---- issue stage 0 ----
    {
        const uint32_t bufA = tbase, bufB = tbase + 16384u;
#pragma unroll
        for (int i = 0; i < 4; i++) {
            uint32_t off = swz(lrow[i] * 128 + lkc * 16);
            CP_ASYNC16(bufA + off, (const char*)(gA + (size_t)lrow[i] * KTOT) + lkc * 16);
        }
        if (!diag) {
#pragma unroll
            for (int i = 0; i < 4; i++) {
                uint32_t off = swz(lrow[i] * 128 + lkc * 16);
                CP_ASYNC16(bufB + off, (const char*)(gB + (size_t)lrow[i] * KTOT) + lkc * 16);
            }
        }
        CP_COMMIT();
    }

#pragma unroll 1
    for (int c = 0; c < NCHUNK; c++) {
        if (c + 1 < NCHUNK) {
            const uint32_t bufA = tbase + ((c + 1) & 1) * 32768u;
            const uint32_t bufB = bufA + 16384u;
            const char* srcA = (const char*)(gA + (c + 1) * KCH);
            const char* srcB = (const char*)(gB + (c + 1) * KCH);
#pragma unroll
            for (int i = 0; i < 4; i++) {
                uint32_t off = swz(lrow[i] * 128 + lkc * 16);
                CP_ASYNC16(bufA + off, srcA + (size_t)lrow[i] * KTOT * 2 + lkc * 16);
            }
            if (!diag) {
#pragma unroll
                for (int i = 0; i < 4; i++) {
                    uint32_t off = swz(lrow[i] * 128 + lkc * 16);
                    CP_ASYNC16(bufB + off, srcB + (size_t)lrow[i] * KTOT * 2 + lkc * 16);
                }
            }
            CP_COMMIT();
            CP_WAIT(1);
        } else {
            CP_WAIT(0);
        }
        __syncthreads();

        const uint32_t bA = tbase + (c & 1) * 32768u;
        const uint32_t bB = diag ? bA : bA + 16384u;

#pragma unroll
        for (int ks = 0; ks < 4; ks++) {
            uint32_t afr[4][4], bfr[4][2];
#pragma unroll
            for (int mt = 0; mt < 4; mt++) {
                int row = m0w + mt * 16 + (lid & 15);
                int ch = ks * 2 + (lid >> 4);
                ldmatrix_x4(afr[mt][0], afr[mt][1], afr[mt][2], afr[mt][3],
                            bA + swz(row * 128 + ch * 16));
            }
#pragma unroll
            for (int nt = 0; nt < 4; nt++) {
                int row = n0w + nt * 8 + (lid & 7);
                int ch = ks * 2 + ((lid >> 3) & 1);
                ldmatrix_x2(bfr[nt][0], bfr[nt][1], bB + swz(row * 128 + ch * 16));
            }
#pragma unroll
            for (int mt = 0; mt < 4; mt++)
#pragma unroll
                for (int nt = 0; nt < 4; nt++)
                    mma_f16(acc[mt][nt], afr[mt], bfr[nt]);
        }
        __syncthreads();
    }

    // -------- epilogue from register fragments --------
    const int gID = lid >> 2;     // 0..7
    const int tig = lid & 3;      // 0..3

    float rs[4][2], cs[4][2];
#pragma unroll
    for (int x = 0; x < 4; x++) { rs[x][0] = rs[x][1] = 0.0f; cs[x][0] = cs[x][1] = 0.0f; }

#pragma unroll
    for (int mt = 0; mt < 4; mt++) {
        const int r0 = m0w + mt * 16 + gID;
        const int r1 = r0 + 8;
        const float mi0 = sMagI[r0], mi1 = sMagI[r1];
        const int li0 = sLabI[r0], li1 = sLabI[r1];
        const int gi_0 = gi0 + r0, gi_1 = gi0 + r1;
#pragma unroll
        for (int nt = 0; nt < 4; nt++) {
            const int c0 = n0w + nt * 8 + tig * 2;
            const int c1 = c0 + 1;
            const float mj0 = sMagJ[c0], mj1 = sMagJ[c1];
            const int lj0 = sLabJ[c0], lj1 = sLabJ[c1];
            const int gj_0 = gj0 + c0, gj_1 = gj0 + c1;

#define PROC(SIM, MI, LI, GI, MJ, LJ, GJ, RSUM, CSUM)                          \
            {                                                                  \
                float d2 = fmaxf((MI) + (MJ)-2.0f * (SIM), 0.0f);              \
                float dist = fast_dist(d2);                                    \
                if ((LI) != (LJ)) {                                            \
                    float e = (dist > 0.0f) ? __expf(MARGIN - dist) : 0.0f;    \
                    RSUM += e;                                                 \
                    CSUM += e;                                                 \
                } else if ((GI) < (GJ)) {                                      \
                    unsigned p = atomicAdd(&sNpos, 1u);                        \
                    unsigned key = ((unsigned)(GI) << 12) | (unsigned)(GJ);    \
                    if (p < CAP) { sPosKey[p] = key; sPosDist[p] = dist; }     \
                    else {                                                     \
                        unsigned q = atomicAdd(&g_npos, 1u);                   \
                        g_pos_key[q] = key;                                    \
                        g_pos_dist[q] = dist;                                  \
                    }                                                          \
                }                                                              \
            }
            PROC(acc[mt][nt][0], mi0, li0, gi_0, mj0, lj0, gj_0, rs[mt][0], cs[nt][0]);
            PROC(acc[mt][nt][1], mi0, li0, gi_0, mj1, lj1, gj_1, rs[mt][0], cs[nt][1]);
            PROC(acc[mt][nt][2], mi1, li1, gi_1, mj0, lj0, gj_0, rs[mt][1], cs[nt][0]);
            PROC(acc[mt][nt][3], mi1, li1, gi_1, mj1, lj1, gj_1, rs[mt][1], cs[nt][1]);
#undef PROC
        }
    }

    // row sums: reduce across lanes with same gID (xor low 2 bits)
#pragma unroll
    for (int mt = 0; mt < 4; mt++) {
        float v0 = rs[mt][0], v1 = rs[mt][1];
        v0 += __shfl_xor_sync(0xffffffffu, v0, 1);
        v0 += __shfl_xor_sync(0xffffffffu, v0, 2);
        v1 += __shfl_xor_sync(0xffffffffu, v1, 1);
        v1 += __shfl_xor_sync(0xffffffffu, v1, 2);
        if (tig == 0) {
            atomicAdd(&sRow[m0w + mt * 16 + gID], v0);
            atomicAdd(&sRow[m0w + mt * 16 + gID + 8], v1);
        }
    }
    // col sums: reduce across gID (xor bits 2..4); skip for diagonal tiles
    if (!diag) {
#pragma unroll
        for (int nt = 0; nt < 4; nt++) {
            float w0 = cs[nt][0], w1 = cs[nt][1];
            w0 += __shfl_xor_sync(0xffffffffu, w0, 4);
            w0 += __shfl_xor_sync(0xffffffffu, w0, 8);
            w0 += __shfl_xor_sync(0xffffffffu, w0, 16);
            w1 += __shfl_xor_sync(0xffffffffu, w1, 4);
            w1 += __shfl_xor_sync(0xffffffffu, w1, 8);
            w1 += __shfl_xor_sync(0xffffffffu, w1, 16);
            if (lid < 4) {
                atomicAdd(&sCol[n0w + nt * 8 + lid * 2], w0);
                atomicAdd(&sCol[n0w + nt * 8 + lid * 2 + 1], w1);
            }
        }
    }
    __syncthreads();

    if (tid < TILE) {
        atomicAdd(&g_rowneg[gi0 + tid], sRow[tid]);
        if (!diag) atomicAdd(&g_rowneg[gj0 + tid], sCol[tid]);
    }

    // flush buffered positive pairs with one reservation
    if (tid == 0) {
        unsigned np = sNpos < CAP ? sNpos : CAP;
        sBase = atomicAdd(&g_npos, np);
    }
    __syncthreads();
    const unsigned np = sNpos < CAP ? sNpos : CAP;
    for (unsigned k2 = tid; k2 < np; k2 += GTHREADS) {
        g_pos_key[sBase + k2] = sPosKey[k2];
        g_pos_dist[sBase + k2] = sPosDist[k2];
    }
}

// ---------------- positive-pair loss + fused finalize (last block) ----------------
__global__ void k_loss2(float* __restrict__ out) {
    const unsigned total = g_npos;
    double lsum = 0.0;
    for (unsigned t = blockIdx.x * blockDim.x + threadIdx.x; t < total;
         t += gridDim.x * blockDim.x) {
        unsigned key = g_pos_key[t];
        float dist = g_pos_dist[t];
        int i = key >> 12;
        int j = key & 4095;
        float J = logf(g_rowneg[i] + g_rowneg[j]) + dist;
        float l = fmaxf(J, 0.0f);
        lsum += (double)l * (double)l;
    }
    __shared__ double sl[256];
    __shared__ unsigned sDone;
    int tid = threadIdx.x;
    sl[tid] = lsum;
    __syncthreads();
    for (int s = 128; s > 0; s >>= 1) {
        if (tid < s) sl[tid] += sl[tid + s];
        __syncthreads();
    }
    if (tid == 0) {
        if (sl[0] != 0.0) atomicAdd(&g_loss, sl[0]);
        __threadfence();
        sDone = atomicAdd(&g_ldone, 1u);
    }
    __syncthreads();
    if (sDone == gridDim.x - 1 && tid == 0) {
        __threadfence();
        out[0] = (float)(g_loss / (double)(2ULL * (unsigned long long)total));
    }
}

extern "C" void kernel_launch(void* const* d_in, const int* in_sizes, int n_in,
                              void* d_out, int out_size) {
    const float* X = (const float*)d_in[0];
    const int* lab = (const int*)d_in[1];
    float* out = (float*)d_out;

    cudaFuncSetAttribute(k_gemm, cudaFuncAttributeMaxDynamicSharedMemorySize, 66560);

    k_prep<<<N / 8, 256>>>(X);
    k_gemm<<<NPAIR_TILES, GTHREADS, 66560>>>(lab);
    k_loss2<<<LGRID, 256>>>(out);
}